// round 14
// baseline (speedup 1.0000x reference)
#include <cuda_runtime.h>

typedef unsigned long long u64;

__device__ __forceinline__ u64 pk2(float lo, float hi) {
    u64 r; asm("mov.b64 %0,{%1,%2};" : "=l"(r) : "f"(lo), "f"(hi)); return r;
}
__device__ __forceinline__ float2 up2(u64 v) {
    float2 f; asm("mov.b64 {%0,%1},%2;" : "=f"(f.x), "=f"(f.y) : "l"(v)); return f;
}
__device__ __forceinline__ u64 fma2(u64 a, u64 b, u64 c) {
    u64 d; asm("fma.rn.f32x2 %0,%1,%2,%3;" : "=l"(d) : "l"(a), "l"(b), "l"(c)); return d;
}
__device__ __forceinline__ u64 add2(u64 a, u64 b) {
    u64 d; asm("add.rn.f32x2 %0,%1,%2;" : "=l"(d) : "l"(a), "l"(b)); return d;
}
__device__ __forceinline__ u64 clamp2(u64 v) {
    float2 f = up2(v);
    f.x = fminf(fmaxf(f.x, -1.0f), 1.0f);
    f.y = fminf(fmaxf(f.y, -1.0f), 1.0f);
    return pk2(f.x, f.y);
}
__device__ __forceinline__ u64 shfl_xor64(u64 v) {
    return (u64)__shfl_xor_sync(0xffffffffu, (unsigned long long)v, 1);
}

#define NPMAX 65536
// transposed input, interleaved col-pairs: pair cp, sample-pair t ->
//   ulonglong2{ pack(col 2cp, t), pack(col 2cp+1, t) }   (193 col-pairs)
__device__ u64 g_T2[(size_t)2 * 193 * NPMAX];   // 202 MB
// sight scratch: ulonglong2 row r (0..143): {sight[2r] pair, sight[2r+1] pair}
__device__ u64 g_S[(size_t)144 * NPMAX];        // 75.5 MB

// ------------------------- transpose + pack kernel -------------------------
__global__ void transpose_kernel(const float* __restrict__ inp, int np)
{
    __shared__ float tile[64][33];
    int bx = blockIdx.x;
    int by = blockIdx.y;
    int tid = threadIdx.x;
    int lx = tid & 31, ly = tid >> 5;
    int col = bx * 32 + lx;

    #pragma unroll
    for (int i = 0; i < 8; i++) {
        int r = ly + i * 8;
        float v = 0.0f;
        if (col < 385) v = inp[(size_t)(by * 64 + r) * 385 + col];
        tile[r][lx] = v;
    }
    __syncthreads();

    int pl = tid & 31;
    int cl = tid >> 5;
    ulonglong2* T2 = reinterpret_cast<ulonglong2*>(g_T2);
    #pragma unroll
    for (int i = 0; i < 2; i++) {
        int cpl = cl + i * 8;
        int c   = cpl * 2;
        int gcp = bx * 16 + cpl;
        if (gcp < 193) {
            u64 lo = pk2(tile[2 * pl][c],     tile[2 * pl + 1][c]);
            u64 hi = pk2(tile[2 * pl][c + 1], tile[2 * pl + 1][c + 1]);
            T2[(size_t)gcp * np + by * 32 + pl] = make_ulonglong2(lo, hi);
        }
    }
}

// ------------------------------ conv kernel -------------------------------
// Thread pairs (2u, 2u+1) share TWO sample-pairs t0=u, t1=u+nq (4 samples);
// p=tid&1 selects neuron half of L1 and, post-exchange, the window (A/B).
#define A_W1 0      // 648
#define A_B1 648    // 12
#define A_W2 660    // 144
#define A_B2 804    // 12
#define A_W3 816    // 48
#define A_B3 864    // 4
#define A_N  868

__global__ void __launch_bounds__(128, 4) conv_kernel(
    const float* __restrict__ W1, const float* __restrict__ b1,
    const float* __restrict__ W2, const float* __restrict__ b2,
    const float* __restrict__ W3, const float* __restrict__ b3,
    int np)
{
    __shared__ __align__(16) u64 sw[A_N];
    int tid = threadIdx.x;
    for (int i = tid; i < 648; i += 128) { float v = W1[i]; sw[A_W1+i] = pk2(v,v); }
    for (int i = tid; i < 12;  i += 128) { sw[A_B1+i] = pk2(b1[i],b1[i]);
                                           sw[A_B2+i] = pk2(b2[i],b2[i]); }
    for (int i = tid; i < 144; i += 128) { sw[A_W2+i] = pk2(W2[i],W2[i]); }
    for (int i = tid; i < 48;  i += 128) { sw[A_W3+i] = pk2(W3[i],W3[i]); }
    if (tid < 4) sw[A_B3+tid] = pk2(b3[tid],b3[tid]);
    __syncthreads();

    int gtid = blockIdx.x * 128 + tid;
    int u = gtid >> 1;
    int p = gtid & 1;
    int nq = np >> 1;                // 32768 groups
    if (u >= nq) return;
    int t0 = u, t1 = u + nq;
    int np6 = 6 * p;

    const ulonglong2* T2 = reinterpret_cast<const ulonglong2*>(g_T2);
    ulonglong2* S = reinterpret_cast<ulonglong2*>(g_S);

    #pragma unroll 1
    for (int wp = 0; wp < 18; wp++) {
        int x  = wp / 3;
        int yy = (wp - x * 3) * 2;
        int cpb = x * 24 + yy * 3;

        // L1: 6 neurons, windows A/B, sample-pairs 0/1
        u64 hA0[6], hB0[6], hA1[6], hB1[6];
        #pragma unroll
        for (int n = 0; n < 6; n++) {
            u64 b = sw[A_B1 + np6 + n];
            hA0[n] = b; hB0[n] = b; hA1[n] = b; hB1[n] = b;
        }

        #pragma unroll 1
        for (int ox = 0; ox < 3; ox++) {
            const ulonglong2* g0 = T2 + (size_t)(cpb + ox * 24) * np + t0;
            const ulonglong2* g1 = T2 + (size_t)(cpb + ox * 24) * np + t1;
            const u64* wk = sw + A_W1 + ox * 216 + np6;

            u64 v0[12], v1[12];
            #pragma unroll
            for (int i = 0; i < 6; i++) {
                ulonglong2 a = __ldg(g0 + (size_t)i * np);
                ulonglong2 b = __ldg(g1 + (size_t)i * np);
                v0[2*i] = a.x; v0[2*i+1] = a.y;
                v1[2*i] = b.x; v1[2*i+1] = b.y;
            }
            // phase 0
            #pragma unroll
            for (int kk = 0; kk < 6; kk++) {
                u64 va0 = v0[kk], vb0 = v0[kk+6], va1 = v1[kk], vb1 = v1[kk+6];
                const ulonglong2* w2 = reinterpret_cast<const ulonglong2*>(wk + kk * 12);
                #pragma unroll
                for (int n2 = 0; n2 < 3; n2++) {
                    ulonglong2 w = w2[n2];
                    hA0[2*n2]   = fma2(va0, w.x, hA0[2*n2]);
                    hA0[2*n2+1] = fma2(va0, w.y, hA0[2*n2+1]);
                    hB0[2*n2]   = fma2(vb0, w.x, hB0[2*n2]);
                    hB0[2*n2+1] = fma2(vb0, w.y, hB0[2*n2+1]);
                    hA1[2*n2]   = fma2(va1, w.x, hA1[2*n2]);
                    hA1[2*n2+1] = fma2(va1, w.y, hA1[2*n2+1]);
                    hB1[2*n2]   = fma2(vb1, w.x, hB1[2*n2]);
                    hB1[2*n2+1] = fma2(vb1, w.y, hB1[2*n2+1]);
                }
            }
            // phase 1
            #pragma unroll
            for (int i = 0; i < 6; i++) { v0[i] = v0[i+6]; v1[i] = v1[i+6]; }
            #pragma unroll
            for (int i = 0; i < 3; i++) {
                ulonglong2 a = __ldg(g0 + (size_t)(6 + i) * np);
                ulonglong2 b = __ldg(g1 + (size_t)(6 + i) * np);
                v0[6+2*i] = a.x; v0[7+2*i] = a.y;
                v1[6+2*i] = b.x; v1[7+2*i] = b.y;
            }
            #pragma unroll
            for (int kk = 0; kk < 6; kk++) {
                u64 va0 = v0[kk], vb0 = v0[kk+6], va1 = v1[kk], vb1 = v1[kk+6];
                const ulonglong2* w2 = reinterpret_cast<const ulonglong2*>(wk + (6 + kk) * 12);
                #pragma unroll
                for (int n2 = 0; n2 < 3; n2++) {
                    ulonglong2 w = w2[n2];
                    hA0[2*n2]   = fma2(va0, w.x, hA0[2*n2]);
                    hA0[2*n2+1] = fma2(va0, w.y, hA0[2*n2+1]);
                    hB0[2*n2]   = fma2(vb0, w.x, hB0[2*n2]);
                    hB0[2*n2+1] = fma2(vb0, w.y, hB0[2*n2+1]);
                    hA1[2*n2]   = fma2(va1, w.x, hA1[2*n2]);
                    hA1[2*n2+1] = fma2(va1, w.y, hA1[2*n2+1]);
                    hB1[2*n2]   = fma2(vb1, w.x, hB1[2*n2]);
                    hB1[2*n2+1] = fma2(vb1, w.y, hB1[2*n2+1]);
                }
            }
            // phase 2
            #pragma unroll
            for (int i = 0; i < 6; i++) { v0[i] = v0[i+6]; v1[i] = v1[i+6]; }
            #pragma unroll
            for (int i = 0; i < 3; i++) {
                ulonglong2 a = __ldg(g0 + (size_t)(9 + i) * np);
                ulonglong2 b = __ldg(g1 + (size_t)(9 + i) * np);
                v0[6+2*i] = a.x; v0[7+2*i] = a.y;
                v1[6+2*i] = b.x; v1[7+2*i] = b.y;
            }
            #pragma unroll
            for (int kk = 0; kk < 6; kk++) {
                u64 va0 = v0[kk], vb0 = v0[kk+6], va1 = v1[kk], vb1 = v1[kk+6];
                const ulonglong2* w2 = reinterpret_cast<const ulonglong2*>(wk + (12 + kk) * 12);
                #pragma unroll
                for (int n2 = 0; n2 < 3; n2++) {
                    ulonglong2 w = w2[n2];
                    hA0[2*n2]   = fma2(va0, w.x, hA0[2*n2]);
                    hA0[2*n2+1] = fma2(va0, w.y, hA0[2*n2+1]);
                    hB0[2*n2]   = fma2(vb0, w.x, hB0[2*n2]);
                    hB0[2*n2+1] = fma2(vb0, w.y, hB0[2*n2+1]);
                    hA1[2*n2]   = fma2(va1, w.x, hA1[2*n2]);
                    hA1[2*n2+1] = fma2(va1, w.y, hA1[2*n2+1]);
                    hB1[2*n2]   = fma2(vb1, w.x, hB1[2*n2]);
                    hB1[2*n2+1] = fma2(vb1, w.y, hB1[2*n2+1]);
                }
            }
        }
        #pragma unroll
        for (int n = 0; n < 6; n++) {
            hA0[n] = clamp2(hA0[n]); hB0[n] = clamp2(hB0[n]);
            hA1[n] = clamp2(hA1[n]); hB1[n] = clamp2(hB1[n]);
        }

        // exchange: even thread keeps winA h[12], odd winB, per sample-pair
        u64 h0[12], h1[12];
        #pragma unroll
        for (int i = 0; i < 6; i++) {
            u64 snd0 = p ? hA0[i] : hB0[i];
            u64 rcv0 = shfl_xor64(snd0);
            h0[i]     = p ? rcv0  : hA0[i];
            h0[6 + i] = p ? hB0[i] : rcv0;
            u64 snd1 = p ? hA1[i] : hB1[i];
            u64 rcv1 = shfl_xor64(snd1);
            h1[i]     = p ? rcv1  : hA1[i];
            h1[6 + i] = p ? hB1[i] : rcv1;
        }

        // layer 2: 12 -> 12, W2 LDS shared across both sample-pairs
        u64 gg0[12], gg1[12];
        #pragma unroll
        for (int n = 0; n < 12; n++) { u64 b = sw[A_B2 + n]; gg0[n] = b; gg1[n] = b; }
        #pragma unroll 4
        for (int k = 0; k < 12; k++) {
            const ulonglong2* w2 = reinterpret_cast<const ulonglong2*>(sw + A_W2 + k * 12);
            #pragma unroll
            for (int n2 = 0; n2 < 6; n2++) {
                ulonglong2 w = w2[n2];
                gg0[2*n2]   = fma2(h0[k], w.x, gg0[2*n2]);
                gg0[2*n2+1] = fma2(h0[k], w.y, gg0[2*n2+1]);
                gg1[2*n2]   = fma2(h1[k], w.x, gg1[2*n2]);
                gg1[2*n2+1] = fma2(h1[k], w.y, gg1[2*n2+1]);
            }
        }
        #pragma unroll
        for (int n = 0; n < 12; n++) { gg0[n] = clamp2(gg0[n]); gg1[n] = clamp2(gg1[n]); }

        // layer 3: 12 -> 4, W3 LDS shared
        u64 s0[4], s1[4];
        #pragma unroll
        for (int q = 0; q < 4; q++) { u64 b = sw[A_B3 + q]; s0[q] = b; s1[q] = b; }
        #pragma unroll
        for (int k = 0; k < 12; k++) {
            const ulonglong2* w2 = reinterpret_cast<const ulonglong2*>(sw + A_W3 + k * 4);
            ulonglong2 w0 = w2[0];
            ulonglong2 w1 = w2[1];
            s0[0] = fma2(gg0[k], w0.x, s0[0]);
            s0[1] = fma2(gg0[k], w0.y, s0[1]);
            s0[2] = fma2(gg0[k], w1.x, s0[2]);
            s0[3] = fma2(gg0[k], w1.y, s0[3]);
            s1[0] = fma2(gg1[k], w0.x, s1[0]);
            s1[1] = fma2(gg1[k], w0.y, s1[1]);
            s1[2] = fma2(gg1[k], w1.x, s1[2]);
            s1[3] = fma2(gg1[k], w1.y, s1[3]);
        }
        #pragma unroll
        for (int q = 0; q < 4; q++) { s0[q] = clamp2(s0[q]); s1[q] = clamp2(s1[q]); }

        // store: window index = wa + p
        int wa = x * 6 + yy;
        size_t row = (size_t)(2 * (wa + p)) * np;
        S[row + t0]      = make_ulonglong2(s0[0], s0[1]);
        S[row + np + t0] = make_ulonglong2(s0[2], s0[3]);
        S[row + t1]      = make_ulonglong2(s1[0], s1[1]);
        S[row + np + t1] = make_ulonglong2(s1[2], s1[3]);
    }
}

// ------------------------------ head kernel -------------------------------
#define H_V1 0      // 4640 (145x32 dup pairs)
#define H_C1 4640   // 32
#define H_C2 4672   // 32
#define H_V3 4704   // 32
#define H_V2 4736   // 1024 (V2 transposed dup pairs: [j][k])
#define H_C3 5760   // 1 (+1 pad)
#define H_N  5762   // 46096 B

__global__ void __launch_bounds__(128, 4) head_kernel(
    const float* __restrict__ V1, const float* __restrict__ c1,
    const float* __restrict__ V2, const float* __restrict__ c2,
    const float* __restrict__ V3, const float* __restrict__ c3,
    float* __restrict__ out, int np)
{
    __shared__ __align__(16) u64 sv[H_N];
    int tid = threadIdx.x;
    for (int i = tid; i < 4640; i += 128) { float v = V1[i]; sv[H_V1+i] = pk2(v,v); }
    for (int i = tid; i < 32;   i += 128) { sv[H_C1+i] = pk2(c1[i],c1[i]);
                                            sv[H_C2+i] = pk2(c2[i],c2[i]);
                                            sv[H_V3+i] = pk2(V3[i],V3[i]); }
    for (int i = tid; i < 1024; i += 128) { int j = i >> 5, k = i & 31;
                                            float v = V2[k*32 + j]; sv[H_V2+i] = pk2(v,v); }
    if (tid == 0) sv[H_C3] = pk2(c3[0], c3[0]);
    __syncthreads();

    int t = blockIdx.x * 128 + tid;
    if (t >= np) return;

    const ulonglong2* S = reinterpret_cast<const ulonglong2*>(g_S);

    u64 acc[32];
    #pragma unroll
    for (int j = 0; j < 32; j++) acc[j] = 0ull;

    #pragma unroll 2
    for (int cp = 0; cp < 72; cp++) {
        ulonglong2 s = __ldg(S + (size_t)cp * np + t);
        const ulonglong2* wk0 = reinterpret_cast<const ulonglong2*>(sv + H_V1 + (2*cp)   * 32);
        const ulonglong2* wk1 = reinterpret_cast<const ulonglong2*>(sv + H_V1 + (2*cp+1) * 32);
        #pragma unroll
        for (int j2 = 0; j2 < 16; j2++) {
            ulonglong2 wA = wk0[j2];
            ulonglong2 wB = wk1[j2];
            acc[2*j2]   = fma2(s.x, wA.x, acc[2*j2]);
            acc[2*j2]   = fma2(s.y, wB.x, acc[2*j2]);
            acc[2*j2+1] = fma2(s.x, wA.y, acc[2*j2+1]);
            acc[2*j2+1] = fma2(s.y, wB.y, acc[2*j2+1]);
        }
    }

    // vision[144] = inp[:,384] (col-pair 192, low element)
    u64 last = g_T2[((size_t)192 * np + t) * 2];
    const u64* v1l = sv + H_V1 + 144 * 32;
    #pragma unroll
    for (int j = 0; j < 32; j++) {
        acc[j] = clamp2(add2(fma2(last, v1l[j], acc[j]), sv[H_C1 + j]));
    }

    // V2 (32->32) + V3 (32->1) fused; V2 stored transposed dup'd pairs
    u64 o = sv[H_C3];
    #pragma unroll 1
    for (int j = 0; j < 32; j++) {
        u64 e = sv[H_C2 + j];
        const ulonglong2* w2 = reinterpret_cast<const ulonglong2*>(sv + H_V2 + j * 32);
        #pragma unroll
        for (int k2 = 0; k2 < 16; k2++) {
            ulonglong2 w = w2[k2];
            e = fma2(acc[2*k2],   w.x, e);
            e = fma2(acc[2*k2+1], w.y, e);
        }
        e = clamp2(e);
        o = fma2(e, sv[H_V3 + j], o);
    }
    o = clamp2(o);

    reinterpret_cast<float2*>(out)[t] = up2(o);
}

extern "C" void kernel_launch(void* const* d_in, const int* in_sizes, int n_in,
                              void* d_out, int out_size) {
    const float* inp = (const float*)d_in[0];
    const float* W1  = (const float*)d_in[1];
    const float* b1  = (const float*)d_in[2];
    const float* W2  = (const float*)d_in[3];
    const float* b2  = (const float*)d_in[4];
    const float* W3  = (const float*)d_in[5];
    const float* b3  = (const float*)d_in[6];
    const float* V1  = (const float*)d_in[7];
    const float* c1  = (const float*)d_in[8];
    const float* V2  = (const float*)d_in[9];
    const float* c2  = (const float*)d_in[10];
    const float* V3  = (const float*)d_in[11];
    const float* c3  = (const float*)d_in[12];

    int B  = in_sizes[0] / 385;   // 131072
    int np = B / 2;               // 65536 sample-pairs

    dim3 tgrid(13, B / 64);
    transpose_kernel<<<tgrid, 256>>>(inp, np);

    int cblocks = (np + 127) / 128;   // np threads: 2 per group of 2 sample-pairs
    conv_kernel<<<cblocks, 128>>>(W1, b1, W2, b2, W3, b3, np);

    int hblocks = (np + 127) / 128;
    head_kernel<<<hblocks, 128>>>(V1, c1, V2, c2, V3, c3, (float*)d_out, np);
}